// round 14
// baseline (speedup 1.0000x reference)
#include <cuda_runtime.h>

#define HW 16384
#define ALPHA 0.17677669529663687f   /* 1/sqrt(32); ALPHA^2 = 1/32 */

// padded h1: 16ch x (5+128) rows x (2+128+2) cols per batch; halo never written => stays 0
#define PROWS 133
#define PCOLS 132
#define PH1   (PROWS*PCOLS)

// ---------------- scratch ----------------
__device__ float g_a[2*4*HW];        // conv1x1 chain output (2,4,128,128)
__device__ float g_P[2*16*HW];       // wf1 @ x  (att-independent part of h1 pre-act)
__device__ float g_att[2*4*HW];      // attention output (for h2out epilogue)
__device__ float g_h1p[2*16*PH1];    // ff first relu, PADDED (zero halo from init)
__device__ float g_q[32*1536*4];     // normalized qk per token
__device__ float g_Gp[32*4*75];      // partial Gram matrices (15 feats x 5 cols, 4 segs)
__device__ float g_part[512*2];      // per-block (sum, sumsq) of a
__device__ float g_weff2[256];       // fused wc@w2    [o][ck]
__device__ float g_beff2[64];
__device__ float g_wfe[64];          // wf1 @ weff2    [m][ck]
__device__ float g_bconst[16];       // wf1 @ beff2 + bf1

// ---------------- a = conv1x1 chain + P = wf1@x + per-block sum/sumsq ----------------
// grid 513: blocks 0..511 = 4 channel-groups x 64 pixels; block 512 = weight fusion
__global__ void __launch_bounds__(256, 4)
a_kernel(const float* __restrict__ x,
         const float* __restrict__ w1a, const float* __restrict__ b1a,
         const float* __restrict__ w1b, const float* __restrict__ b1b,
         const float* __restrict__ w2,  const float* __restrict__ b2,
         const float* __restrict__ wc,  const float* __restrict__ bc,
         const float* __restrict__ wf1, const float* __restrict__ bf1) {
    int t = threadIdx.x;
    if (blockIdx.x == 512) {
        __shared__ float swe[256], sbe[64];
        {
            int o = t >> 2, ck = t & 3;
            float s = 0.f;
            #pragma unroll 8
            for (int c = 0; c < 64; c++) s += wc[o*64+c] * w2[c*4+ck];
            swe[t] = s;
            g_weff2[t] = s;
        }
        if (t < 64) {
            float s = bc[t];
            #pragma unroll 8
            for (int c = 0; c < 64; c++) s += wc[t*64+c] * b2[c];
            sbe[t] = s;
            g_beff2[t] = s;
        }
        __syncthreads();
        if (t < 64) {
            int m = t >> 2, ck = t & 3;
            float s = 0.f;
            #pragma unroll 8
            for (int o = 0; o < 64; o++) s += wf1[m*64+o] * swe[o*4+ck];
            g_wfe[t] = s;
        }
        if (t < 16) {
            float s = bf1[t];
            #pragma unroll 8
            for (int o = 0; o < 64; o++) s += wf1[t*64+o] * sbe[o];
            g_bconst[t] = s;
        }
        return;
    }
    __shared__ float sw[256];
    __shared__ float sb[4];
    __shared__ __align__(16) float swf1t[1024];   // [c][m]
    __shared__ float spart[4*64*5];
    __shared__ float sredP[4*64*17];
    __shared__ float rs[8], rq[8];
    {
        int ck = t >> 6, c = t & 63;
        float s = 0.f;
        #pragma unroll
        for (int j = 0; j < 4; j++) s += w1b[ck*4+j] * w1a[j*64+c];
        sw[ck*64+c] = s;
    }
    if (t < 4) {
        float s = b1b[t];
        #pragma unroll
        for (int j = 0; j < 4; j++) s += w1b[t*4+j] * b1a[j];
        sb[t] = s;
    }
    #pragma unroll
    for (int i = 0; i < 4; i++) {
        int idx = t + i*256;              // coalesced read of wf1[m][c]
        int m = idx >> 6, c = idx & 63;
        swf1t[c*16 + m] = wf1[idx];       // transpose to [c][m]
    }
    __syncthreads();

    int g = t >> 6, pixl = t & 63;
    int p = blockIdx.x*64 + pixl;
    int b = p >> 14, pix = p & 16383;
    const float* xp = x + b*64*HW + pix;
    float p0 = 0.f, p1 = 0.f, p2 = 0.f, p3 = 0.f;
    float accP[16];
    #pragma unroll
    for (int m = 0; m < 16; m++) accP[m] = 0.f;
    #pragma unroll
    for (int i = 0; i < 16; i++) {
        int c = g*16 + i;
        float xv = xp[c*HW];
        p0 += sw[c]*xv; p1 += sw[64+c]*xv; p2 += sw[128+c]*xv; p3 += sw[192+c]*xv;
        const float4* w4 = reinterpret_cast<const float4*>(&swf1t[c*16]);
        float4 wa = w4[0], wb = w4[1], wc4 = w4[2], wd = w4[3];
        accP[0]  += wa.x*xv;  accP[1]  += wa.y*xv;  accP[2]  += wa.z*xv;  accP[3]  += wa.w*xv;
        accP[4]  += wb.x*xv;  accP[5]  += wb.y*xv;  accP[6]  += wb.z*xv;  accP[7]  += wb.w*xv;
        accP[8]  += wc4.x*xv; accP[9]  += wc4.y*xv; accP[10] += wc4.z*xv; accP[11] += wc4.w*xv;
        accP[12] += wd.x*xv;  accP[13] += wd.y*xv;  accP[14] += wd.z*xv;  accP[15] += wd.w*xv;
    }
    float* sp = &spart[(g*64 + pixl)*5];
    sp[0] = p0; sp[1] = p1; sp[2] = p2; sp[3] = p3;
    float* spP = &sredP[(g*64 + pixl)*17];
    #pragma unroll
    for (int m = 0; m < 16; m++) spP[m] = accP[m];
    __syncthreads();

    float a = sb[g];
    #pragma unroll
    for (int gg = 0; gg < 4; gg++) a += spart[(gg*64 + pixl)*5 + g];
    g_a[(b*4 + g)*HW + pix] = a;

    // finalize P channels m = g*4 .. g*4+3 (no bias — folded into bconst)
    float* Pp = g_P + b*16*HW + pix;
    #pragma unroll
    for (int j = 0; j < 4; j++) {
        int m = g*4 + j;
        float s = 0.f;
        #pragma unroll
        for (int gg = 0; gg < 4; gg++) s += sredP[(gg*64 + pixl)*17 + m];
        Pp[m*HW] = s;
    }

    float s = a, sq = a*a;
    #pragma unroll
    for (int o = 16; o > 0; o >>= 1) {
        s  += __shfl_down_sync(0xffffffffu, s,  o);
        sq += __shfl_down_sync(0xffffffffu, sq, o);
    }
    int wid = t >> 5, lane = t & 31;
    if (lane == 0) { rs[wid] = s; rq[wid] = sq; }
    __syncthreads();
    if (t == 0) {
        float ts = 0.f, tq = 0.f;
        #pragma unroll
        for (int w = 0; w < 8; w++) { ts += rs[w]; tq += rq[w]; }
        g_part[blockIdx.x*2]   = ts;
        g_part[blockIdx.x*2+1] = tq;
    }
}

// ---------------- attention pass 1: tokens -> q -> partial Gram ----------------
__global__ void attn1_kernel(const float* __restrict__ wqk) {
    __shared__ float st[384*4];
    __shared__ float sphi[384*16];
    __shared__ float swqk[16];
    __shared__ float sstat[2];
    __shared__ float sGc[4*80];
    int t = threadIdx.x;
    int seg = blockIdx.x;
    int batch2 = blockIdx.y;
    int b = batch2 >> 4, j = batch2 & 15;
    int c_idx = j >> 2, f1 = j & 3;
    if (t >= 352 && t < 368) swqk[t-352] = wqk[t-352];

    cudaGridDependencySynchronize();   // a_kernel complete beyond this point

    if (t < 32) {
        float s = 0.f, sq = 0.f;
        #pragma unroll
        for (int i = 0; i < 8; i++) {
            int blk = b*256 + t + i*32;
            s  += g_part[blk*2];
            sq += g_part[blk*2+1];
        }
        #pragma unroll
        for (int o = 16; o > 0; o >>= 1) {
            s  += __shfl_down_sync(0xffffffffu, s,  o);
            sq += __shfl_down_sync(0xffffffffu, sq, o);
        }
        if (t == 0) {
            const float n = 4.f * 192.f * 128.f;
            float mu  = s / n;
            float var = sq / n - mu*mu;
            sstat[0] = mu;
            sstat[1] = rsqrtf(var + 1e-5f);
        }
    }

    int l = seg*384 + t;
    int gh = l >> 5, gw = l & 31;
    int r = gh*4 + f1;
    float v0 = 0.f, v1 = 0.f, v2 = 0.f, v3 = 0.f;
    if (r >= 64) {
        float4 v = *reinterpret_cast<const float4*>(
            &g_a[((b*4 + c_idx)*128 + (r-64))*128 + gw*4]);
        v0 = v.x; v1 = v.y; v2 = v.z; v3 = v.w;
    }
    __syncthreads();
    {
        float mu = sstat[0], rsg = sstat[1];
        float t0 = (v0 - mu)*rsg, t1 = (v1 - mu)*rsg, t2 = (v2 - mu)*rsg, t3 = (v3 - mu)*rsg;
        float q0 = t0*swqk[0] + t1*swqk[4] + t2*swqk[8]  + t3*swqk[12];
        float q1 = t0*swqk[1] + t1*swqk[5] + t2*swqk[9]  + t3*swqk[13];
        float q2 = t0*swqk[2] + t1*swqk[6] + t2*swqk[10] + t3*swqk[14];
        float q3 = t0*swqk[3] + t1*swqk[7] + t2*swqk[11] + t3*swqk[15];
        float inv = 1.f / (sqrtf(q0*q0 + q1*q1 + q2*q2 + q3*q3) + 1e-8f);
        q0 *= inv; q1 *= inv; q2 *= inv; q3 *= inv;
        st[t*4+0] = t0; st[t*4+1] = t1; st[t*4+2] = t2; st[t*4+3] = t3;
        float* ph = &sphi[t*16];
        ph[0]  = 1.f;
        ph[1]  = ALPHA * q3;
        ph[2]  = 0.015625f * q3*q3;
        ph[3]  = ALPHA * q2;
        ph[4]  = 0.03125f  * q2*q3;
        ph[5]  = 0.015625f * q2*q2;
        ph[6]  = ALPHA * q1;
        ph[7]  = 0.03125f  * q1*q3;
        ph[8]  = 0.03125f  * q1*q2;
        ph[9]  = 0.015625f * q1*q1;
        ph[10] = ALPHA * q0;
        ph[11] = 0.03125f  * q0*q3;
        ph[12] = 0.03125f  * q0*q2;
        ph[13] = 0.03125f  * q0*q1;
        ph[14] = 0.015625f * q0*q0;
        *reinterpret_cast<float4*>(&g_q[(batch2*1536 + l)*4]) = make_float4(q0,q1,q2,q3);
    }
    __syncthreads();

    if (t < 300) {
        int chunk = t / 75, out = t - chunk*75;
        int fi = out / 5, mi = out - fi*5;
        int base = chunk * 96;
        float sum = 0.f;
        #pragma unroll 4
        for (int i = 0; i < 96; i++) {
            int lt = base + i;
            float m  = sphi[lt*16 + fi];
            float mv = (mi < 4) ? st[lt*4 + mi] : 1.f;
            sum += m * mv;
        }
        sGc[chunk*80 + out] = sum;
    }
    __syncthreads();
    if (t < 75) {
        float g = sGc[t] + sGc[80+t] + sGc[160+t] + sGc[240+t];
        g_Gp[(batch2*4 + seg)*75 + t] = g;
    }
}

// ---------------- h1 kernel: attention readout + h1 = relu(P + wfe@att + bconst) ----------------
// grid 512, block 256 = 4 groups x 64 pixels (half row). Also stores att for h2out.
__global__ void __launch_bounds__(256, 4)
h1_kernel() {
    __shared__ float satt[4*64];
    __shared__ float sG4[4*76];
    __shared__ float swfe[64], sbc[16];
    int t = threadIdx.x;

    cudaGridDependencySynchronize();     // attn1 (and transitively a_kernel) complete

    if (t < 64) swfe[t] = g_wfe[t];
    if (t < 16) sbc[t] = g_bconst[t];

    int pbase = blockIdx.x * 64;
    int b = pbase >> 14;
    int pixbase = pbase & 16383;
    int row = pixbase >> 7;
    int wbase = pixbase & 127;           // 0 or 64
    int bb = b*16 + (row & 3)*4;
    int gh = row >> 2;
    int g = t >> 6, pixl = t & 63;
    int pix = pixbase + pixl;

    for (int i = t; i < 300; i += 256) {
        int cc = i / 75, f = i - cc*75;
        int batch2 = bb + cc;
        float s = 0.f;
        #pragma unroll
        for (int sgi = 0; sgi < 4; sgi++) s += g_Gp[(batch2*4 + sgi)*75 + f];
        sG4[cc*76 + f] = s;
    }
    __syncthreads();

    if (t < 64) {
        int col = wbase + t;
        int cc = col & 3, gw = col >> 2;
        int l = gh*32 + gw;
        float4 qv = *reinterpret_cast<const float4*>(&g_q[((bb+cc)*1536 + l)*4]);
        float q0 = qv.x, q1 = qv.y, q2 = qv.z, q3 = qv.w;
        float mono[15];
        mono[0]  = 1.f;
        mono[1]  = q3;  mono[2]  = q3*q3;
        mono[3]  = q2;  mono[4]  = q2*q3;  mono[5]  = q2*q2;
        mono[6]  = q1;  mono[7]  = q1*q3;  mono[8]  = q1*q2;  mono[9]  = q1*q1;
        mono[10] = q0;  mono[11] = q0*q3;  mono[12] = q0*q2;  mono[13] = q0*q1;  mono[14] = q0*q0;
        const float* G = &sG4[cc*76];
        float a0=0.f, a1=0.f, a2=0.f, a3=0.f, a4=0.f;
        #pragma unroll
        for (int f = 0; f < 15; f++) {
            float m = mono[f];
            a0 += m * G[f*5+0];
            a1 += m * G[f*5+1];
            a2 += m * G[f*5+2];
            a3 += m * G[f*5+3];
            a4 += m * G[f*5+4];
        }
        float inv = 1.f / a4;
        satt[t]       = a0*inv;
        satt[64+t]    = a1*inv;
        satt[128+t]   = a2*inv;
        satt[192+t]   = a3*inv;
    }
    __syncthreads();

    // store att (channel g) for h2out's epilogue
    g_att[(b*4 + g)*HW + pix] = satt[g*64 + pixl];

    // h1 channels m = g*4 .. g*4+3
    float at0 = satt[pixl], at1 = satt[64+pixl], at2 = satt[128+pixl], at3 = satt[192+pixl];
    const float* Pp = g_P + b*16*HW + pix;
    int col = wbase + pixl;
    #pragma unroll
    for (int j = 0; j < 4; j++) {
        int m = g*4 + j;
        float h = Pp[m*HW] + sbc[m]
                + swfe[m*4]*at0 + swfe[m*4+1]*at1 + swfe[m*4+2]*at2 + swfe[m*4+3]*at3;
        g_h1p[(b*16 + m)*PH1 + (row + 5)*PCOLS + (col + 2)] = fmaxf(h, 0.f);
    }
}

// ---------------- fused: dilated 3x3 conv + relu + final 1x1 + residual ----------------
// grid 512, block 256 = 4 groups x 64 pixels; branchless conv via padded h1.
// Epilogue reconstructs y = x + weff2@att + beff2 inline (y buffer eliminated).
__global__ void __launch_bounds__(256, 4)
h2out_kernel(const float* __restrict__ x,
             const float* __restrict__ wf2, const float* __restrict__ bf2,
             const float* __restrict__ wf3, const float* __restrict__ bf3,
             float* __restrict__ out) {
    __shared__ __align__(16) float sw2t[2304];  // [ci][tap][m]
    __shared__ float sb[16];
    __shared__ __align__(16) float sw3[1024];   // [o][m]
    __shared__ float sb3[64];
    __shared__ float swe2[256], sbe2[64];
    __shared__ float satt4[256];
    __shared__ float sred[4*64*17];
    __shared__ float sfin[64*17];
    int t = threadIdx.x;
    for (int i = t; i < 2304; i += 256) {
        int ci = i / 144, rem = i - ci*144;
        int tap = rem >> 4, m = rem & 15;
        sw2t[i] = wf2[(m*16 + ci)*9 + tap];
    }
    for (int i = t; i < 1024; i += 256) sw3[i] = wf3[i];
    if (t < 16) sb[t] = bf2[t];
    if (t < 64) sb3[t] = bf3[t];

    cudaGridDependencySynchronize();     // h1_kernel complete beyond this point

    int pbase = blockIdx.x * 64;
    int b = pbase >> 14;
    int pixbase = pbase & 16383;
    swe2[t] = g_weff2[t];
    if (t < 64) sbe2[t] = g_beff2[t];
    satt4[t] = g_att[(b*4 + (t >> 6))*HW + pixbase + (t & 63)];
    __syncthreads();

    int g = t >> 6, pixl = t & 63;
    int pix = pixbase + pixl;
    int h = pix >> 7, w = pix & 127;

    float vload[4][9];
    #pragma unroll
    for (int i = 0; i < 4; i++) {
        int ci = g*4 + i;
        const float* tb = &g_h1p[(b*16 + ci)*PH1];
        #pragma unroll
        for (int kh = 0; kh < 3; kh++)
            #pragma unroll
            for (int kw = 0; kw < 3; kw++)
                vload[i][kh*3+kw] = tb[(h + 2*kh)*PCOLS + (w + 2*kw)];
    }

    float acc[16];
    #pragma unroll
    for (int m = 0; m < 16; m++) acc[m] = 0.f;
    #pragma unroll
    for (int i = 0; i < 4; i++) {
        int ci = g*4 + i;
        const float* wb = &sw2t[ci*144];
        #pragma unroll
        for (int tap = 0; tap < 9; tap++) {
            float v = vload[i][tap];
            const float4* w4 = reinterpret_cast<const float4*>(&wb[tap*16]);
            float4 wa = w4[0], wbv = w4[1], wcv = w4[2], wd = w4[3];
            acc[0]  += wa.x*v;  acc[1]  += wa.y*v;  acc[2]  += wa.z*v;  acc[3]  += wa.w*v;
            acc[4]  += wbv.x*v; acc[5]  += wbv.y*v; acc[6]  += wbv.z*v; acc[7]  += wbv.w*v;
            acc[8]  += wcv.x*v; acc[9]  += wcv.y*v; acc[10] += wcv.z*v; acc[11] += wcv.w*v;
            acc[12] += wd.x*v;  acc[13] += wd.y*v;  acc[14] += wd.z*v;  acc[15] += wd.w*v;
        }
    }
    float* sp = &sred[(g*64 + pixl)*17];
    #pragma unroll
    for (int m = 0; m < 16; m++) sp[m] = acc[m];
    __syncthreads();

    #pragma unroll
    for (int i = 0; i < 4; i++) {
        int m = g*4 + i;
        float v = sb[m];
        #pragma unroll
        for (int gg = 0; gg < 4; gg++) v += sred[(gg*64 + pixl)*17 + m];
        sfin[pixl*17 + m] = fmaxf(v, 0.f);
    }
    __syncthreads();

    float h2v[16];
    #pragma unroll
    for (int m = 0; m < 16; m++) h2v[m] = sfin[pixl*17 + m];
    float at0 = satt4[pixl], at1 = satt4[64+pixl], at2 = satt4[128+pixl], at3 = satt4[192+pixl];
    const float* xp = x + b*64*HW + pix;
    float*       op = out + b*64*HW + pix;
    #pragma unroll
    for (int i = 0; i < 16; i++) {
        int o = g*16 + i;
        const float4* w4 = reinterpret_cast<const float4*>(&sw3[o*16]);
        float4 wa = w4[0], wbv = w4[1], wcv = w4[2], wd = w4[3];
        float s = xp[o*HW] + sbe2[o] + sb3[o]
                + swe2[o*4]*at0 + swe2[o*4+1]*at1 + swe2[o*4+2]*at2 + swe2[o*4+3]*at3;
        s += wa.x*h2v[0]   + wa.y*h2v[1]   + wa.z*h2v[2]   + wa.w*h2v[3];
        s += wbv.x*h2v[4]  + wbv.y*h2v[5]  + wbv.z*h2v[6]  + wbv.w*h2v[7];
        s += wcv.x*h2v[8]  + wcv.y*h2v[9]  + wcv.z*h2v[10] + wcv.w*h2v[11];
        s += wd.x*h2v[12]  + wd.y*h2v[13]  + wd.z*h2v[14]  + wd.w*h2v[15];
        op[o*HW] = s;
    }
}

extern "C" void kernel_launch(void* const* d_in, const int* in_sizes, int n_in,
                              void* d_out, int out_size) {
    const float* x   = (const float*)d_in[0];
    const float* w1a = (const float*)d_in[1];
    const float* b1a = (const float*)d_in[2];
    const float* w1b = (const float*)d_in[3];
    const float* b1b = (const float*)d_in[4];
    const float* wqk = (const float*)d_in[5];
    const float* w2  = (const float*)d_in[6];
    const float* b2  = (const float*)d_in[7];
    const float* wc  = (const float*)d_in[8];
    const float* bc  = (const float*)d_in[9];
    const float* wf1 = (const float*)d_in[10];
    const float* bf1 = (const float*)d_in[11];
    const float* wf2 = (const float*)d_in[12];
    const float* bf2 = (const float*)d_in[13];
    const float* wf3 = (const float*)d_in[14];
    const float* bf3 = (const float*)d_in[15];
    float* out = (float*)d_out;

    a_kernel<<<513, 256>>>(x, w1a, b1a, w1b, b1b, w2, b2, wc, bc, wf1, bf1);

    cudaLaunchAttribute attr[1];
    attr[0].id = cudaLaunchAttributeProgrammaticStreamSerialization;
    attr[0].val.programmaticStreamSerializationAllowed = 1;

    {
        cudaLaunchConfig_t cfg = {};
        cfg.gridDim = dim3(4, 32); cfg.blockDim = dim3(384);
        cfg.stream = 0; cfg.attrs = attr; cfg.numAttrs = 1;
        cudaLaunchKernelEx(&cfg, attn1_kernel, wqk);
    }
    {
        cudaLaunchConfig_t cfg = {};
        cfg.gridDim = dim3(512); cfg.blockDim = dim3(256);
        cfg.stream = 0; cfg.attrs = attr; cfg.numAttrs = 1;
        cudaLaunchKernelEx(&cfg, h1_kernel);
    }
    {
        cudaLaunchConfig_t cfg = {};
        cfg.gridDim = dim3(512); cfg.blockDim = dim3(256);
        cfg.stream = 0; cfg.attrs = attr; cfg.numAttrs = 1;
        cudaLaunchKernelEx(&cfg, h2out_kernel, x, wf2, bf2, wf3, bf3, out);
    }
}

// round 15
// speedup vs baseline: 1.0630x; 1.0630x over previous
#include <cuda_runtime.h>

#define HW 16384
#define ALPHA 0.17677669529663687f   /* 1/sqrt(32); ALPHA^2 = 1/32 */

// padded h1: 16ch x (5+128) rows x (2+128+2) cols per batch; halo never written => stays 0
#define PROWS 133
#define PCOLS 132
#define PH1   (PROWS*PCOLS)

// ---------------- scratch ----------------
__device__ float g_a[2*4*HW];        // conv1x1 chain output (2,4,128,128)
__device__ float g_att[2*4*HW];      // attention output (for h2out epilogue)
__device__ float g_h1p[2*16*PH1];    // ff first relu, PADDED (zero halo from init)
__device__ float g_q[32*1536*4];     // normalized qk per token
__device__ float g_Gp[32*4*75];      // partial Gram matrices (15 feats x 5 cols, 4 segs)
__device__ float g_part[512*2];      // per-block (sum, sumsq) of a
__device__ float g_weff2[256];       // fused wc@w2    [o][ck]
__device__ float g_beff2[64];

// ---------------- a = fused conv1x1 chain + per-block sum/sumsq ----------------
// grid 513: blocks 0..511 = 4 channel-groups x 64 pixels; block 512 = weight fusion
__global__ void a_kernel(const float* __restrict__ x,
                         const float* __restrict__ w1a, const float* __restrict__ b1a,
                         const float* __restrict__ w1b, const float* __restrict__ b1b,
                         const float* __restrict__ w2,  const float* __restrict__ b2,
                         const float* __restrict__ wc,  const float* __restrict__ bc) {
    int t = threadIdx.x;
    if (blockIdx.x == 512) {
        int o = t >> 2, ck = t & 3;
        float s = 0.f;
        #pragma unroll 8
        for (int c = 0; c < 64; c++) s += wc[o*64+c] * w2[c*4+ck];
        g_weff2[o*4+ck] = s;
        if (t < 64) {
            float sbv = bc[t];
            #pragma unroll 8
            for (int c = 0; c < 64; c++) sbv += wc[t*64+c] * b2[c];
            g_beff2[t] = sbv;
        }
        return;
    }
    __shared__ float sw[256];
    __shared__ float sb[4];
    __shared__ float spart[4*64*5];
    __shared__ float rs[8], rq[8];
    {
        int ck = t >> 6, c = t & 63;
        float s = 0.f;
        #pragma unroll
        for (int j = 0; j < 4; j++) s += w1b[ck*4+j] * w1a[j*64+c];
        sw[ck*64+c] = s;
    }
    if (t < 4) {
        float s = b1b[t];
        #pragma unroll
        for (int j = 0; j < 4; j++) s += w1b[t*4+j] * b1a[j];
        sb[t] = s;
    }
    __syncthreads();

    int g = t >> 6, pixl = t & 63;
    int p = blockIdx.x*64 + pixl;
    int b = p >> 14, pix = p & 16383;
    const float* xp = x + b*64*HW + pix;
    float p0 = 0.f, p1 = 0.f, p2 = 0.f, p3 = 0.f;
    #pragma unroll
    for (int i = 0; i < 16; i++) {
        int c = g*16 + i;
        float xv = xp[c*HW];
        p0 += sw[c]*xv; p1 += sw[64+c]*xv; p2 += sw[128+c]*xv; p3 += sw[192+c]*xv;
    }
    float* sp = &spart[(g*64 + pixl)*5];
    sp[0] = p0; sp[1] = p1; sp[2] = p2; sp[3] = p3;
    __syncthreads();

    float a = sb[g];
    #pragma unroll
    for (int gg = 0; gg < 4; gg++) a += spart[(gg*64 + pixl)*5 + g];
    g_a[(b*4 + g)*HW + pix] = a;

    float s = a, sq = a*a;
    #pragma unroll
    for (int o = 16; o > 0; o >>= 1) {
        s  += __shfl_down_sync(0xffffffffu, s,  o);
        sq += __shfl_down_sync(0xffffffffu, sq, o);
    }
    int wid = t >> 5, lane = t & 31;
    if (lane == 0) { rs[wid] = s; rq[wid] = sq; }
    __syncthreads();
    if (t == 0) {
        float ts = 0.f, tq = 0.f;
        #pragma unroll
        for (int w = 0; w < 8; w++) { ts += rs[w]; tq += rq[w]; }
        g_part[blockIdx.x*2]   = ts;
        g_part[blockIdx.x*2+1] = tq;
    }
}

// ---------------- attention pass 1: tokens -> q -> partial Gram ----------------
__global__ void attn1_kernel(const float* __restrict__ wqk) {
    __shared__ float st[384*4];
    __shared__ float sphi[384*16];
    __shared__ float swqk[16];
    __shared__ float sstat[2];
    __shared__ float sGc[4*80];
    int t = threadIdx.x;
    int seg = blockIdx.x;
    int batch2 = blockIdx.y;
    int b = batch2 >> 4, j = batch2 & 15;
    int c_idx = j >> 2, f1 = j & 3;
    if (t >= 352 && t < 368) swqk[t-352] = wqk[t-352];

    cudaGridDependencySynchronize();   // a_kernel complete beyond this point

    if (t < 32) {
        float s = 0.f, sq = 0.f;
        #pragma unroll
        for (int i = 0; i < 8; i++) {
            int blk = b*256 + t + i*32;
            s  += g_part[blk*2];
            sq += g_part[blk*2+1];
        }
        #pragma unroll
        for (int o = 16; o > 0; o >>= 1) {
            s  += __shfl_down_sync(0xffffffffu, s,  o);
            sq += __shfl_down_sync(0xffffffffu, sq, o);
        }
        if (t == 0) {
            const float n = 4.f * 192.f * 128.f;
            float mu  = s / n;
            float var = sq / n - mu*mu;
            sstat[0] = mu;
            sstat[1] = rsqrtf(var + 1e-5f);
        }
    }

    int l = seg*384 + t;
    int gh = l >> 5, gw = l & 31;
    int r = gh*4 + f1;
    float v0 = 0.f, v1 = 0.f, v2 = 0.f, v3 = 0.f;
    if (r >= 64) {
        float4 v = *reinterpret_cast<const float4*>(
            &g_a[((b*4 + c_idx)*128 + (r-64))*128 + gw*4]);
        v0 = v.x; v1 = v.y; v2 = v.z; v3 = v.w;
    }
    __syncthreads();
    {
        float mu = sstat[0], rsg = sstat[1];
        float t0 = (v0 - mu)*rsg, t1 = (v1 - mu)*rsg, t2 = (v2 - mu)*rsg, t3 = (v3 - mu)*rsg;
        float q0 = t0*swqk[0] + t1*swqk[4] + t2*swqk[8]  + t3*swqk[12];
        float q1 = t0*swqk[1] + t1*swqk[5] + t2*swqk[9]  + t3*swqk[13];
        float q2 = t0*swqk[2] + t1*swqk[6] + t2*swqk[10] + t3*swqk[14];
        float q3 = t0*swqk[3] + t1*swqk[7] + t2*swqk[11] + t3*swqk[15];
        float inv = 1.f / (sqrtf(q0*q0 + q1*q1 + q2*q2 + q3*q3) + 1e-8f);
        q0 *= inv; q1 *= inv; q2 *= inv; q3 *= inv;
        st[t*4+0] = t0; st[t*4+1] = t1; st[t*4+2] = t2; st[t*4+3] = t3;
        float* ph = &sphi[t*16];
        ph[0]  = 1.f;
        ph[1]  = ALPHA * q3;
        ph[2]  = 0.015625f * q3*q3;
        ph[3]  = ALPHA * q2;
        ph[4]  = 0.03125f  * q2*q3;
        ph[5]  = 0.015625f * q2*q2;
        ph[6]  = ALPHA * q1;
        ph[7]  = 0.03125f  * q1*q3;
        ph[8]  = 0.03125f  * q1*q2;
        ph[9]  = 0.015625f * q1*q1;
        ph[10] = ALPHA * q0;
        ph[11] = 0.03125f  * q0*q3;
        ph[12] = 0.03125f  * q0*q2;
        ph[13] = 0.03125f  * q0*q1;
        ph[14] = 0.015625f * q0*q0;
        *reinterpret_cast<float4*>(&g_q[(batch2*1536 + l)*4]) = make_float4(q0,q1,q2,q3);
    }
    __syncthreads();

    if (t < 300) {
        int chunk = t / 75, out = t - chunk*75;
        int fi = out / 5, mi = out - fi*5;
        int base = chunk * 96;
        float sum = 0.f;
        #pragma unroll 4
        for (int i = 0; i < 96; i++) {
            int lt = base + i;
            float m  = sphi[lt*16 + fi];
            float mv = (mi < 4) ? st[lt*4 + mi] : 1.f;
            sum += m * mv;
        }
        sGc[chunk*80 + out] = sum;
    }
    __syncthreads();
    if (t < 75) {
        float g = sGc[t] + sGc[80+t] + sGc[160+t] + sGc[240+t];
        g_Gp[(batch2*4 + seg)*75 + t] = g;
    }
}

// ---------------- h1 kernel: att readout + h1 = relu(wf1@(x+proj(att)) + bf1) ----------------
// grid 512, block 256 = 4 groups x 64 pixels. Computes yv in registers, does NOT store y.
// Stores att (for h2out's inline y reconstruction) + padded h1.
__global__ void __launch_bounds__(256, 4)
h1_kernel(const float* __restrict__ x,
          const float* __restrict__ wf1, const float* __restrict__ bf1) {
    __shared__ float swe[256], sbe[64], sbf1[16];
    __shared__ __align__(16) float swf1t[1024];   // transposed [o][m]
    __shared__ float satt[4*64];
    __shared__ float sG4[4*76];
    __shared__ float sred[4*64*17];
    int t = threadIdx.x;
    #pragma unroll
    for (int i = 0; i < 4; i++) {
        int idx = t + i*256;             // coalesced read of wf1[m][o]
        int m = idx >> 6, o = idx & 63;
        swf1t[o*16 + m] = wf1[idx];      // shared scatter (transpose)
    }
    if (t < 16) sbf1[t] = bf1[t];

    cudaGridDependencySynchronize();     // attn1 (and transitively a_kernel) complete

    swe[t] = g_weff2[t];
    if (t < 64) sbe[t] = g_beff2[t];

    int pbase = blockIdx.x * 64;
    int b = pbase >> 14;
    int pixbase = pbase & 16383;
    int row = pixbase >> 7;
    int wbase = pixbase & 127;           // 0 or 64
    int bb = b*16 + (row & 3)*4;
    int gh = row >> 2;
    int g = t >> 6, pixl = t & 63;
    int pix = pixbase + pixl;

    for (int i = t; i < 300; i += 256) {
        int cc = i / 75, f = i - cc*75;
        int batch2 = bb + cc;
        float s = 0.f;
        #pragma unroll
        for (int sgi = 0; sgi < 4; sgi++) s += g_Gp[(batch2*4 + sgi)*75 + f];
        sG4[cc*76 + f] = s;
    }
    __syncthreads();

    if (t < 64) {
        int col = wbase + t;
        int cc = col & 3, gw = col >> 2;
        int l = gh*32 + gw;
        float4 qv = *reinterpret_cast<const float4*>(&g_q[((bb+cc)*1536 + l)*4]);
        float q0 = qv.x, q1 = qv.y, q2 = qv.z, q3 = qv.w;
        float mono[15];
        mono[0]  = 1.f;
        mono[1]  = q3;  mono[2]  = q3*q3;
        mono[3]  = q2;  mono[4]  = q2*q3;  mono[5]  = q2*q2;
        mono[6]  = q1;  mono[7]  = q1*q3;  mono[8]  = q1*q2;  mono[9]  = q1*q1;
        mono[10] = q0;  mono[11] = q0*q3;  mono[12] = q0*q2;  mono[13] = q0*q1;  mono[14] = q0*q0;
        const float* G = &sG4[cc*76];
        float a0=0.f, a1=0.f, a2=0.f, a3=0.f, a4=0.f;
        #pragma unroll
        for (int f = 0; f < 15; f++) {
            float m = mono[f];
            a0 += m * G[f*5+0];
            a1 += m * G[f*5+1];
            a2 += m * G[f*5+2];
            a3 += m * G[f*5+3];
            a4 += m * G[f*5+4];
        }
        float inv = 1.f / a4;
        satt[t]       = a0*inv;
        satt[64+t]    = a1*inv;
        satt[128+t]   = a2*inv;
        satt[192+t]   = a3*inv;
    }
    __syncthreads();

    // store att (channel g) for h2out's epilogue
    g_att[(b*4 + g)*HW + pix] = satt[g*64 + pixl];

    float at0 = satt[pixl], at1 = satt[64+pixl], at2 = satt[128+pixl], at3 = satt[192+pixl];
    float acc[16];
    #pragma unroll
    for (int m = 0; m < 16; m++) acc[m] = 0.f;
    const float* xp = x + b*64*HW + pix;
    #pragma unroll
    for (int i = 0; i < 16; i++) {
        int o = g*16 + i;
        float yv = xp[o*HW] + sbe[o]
                 + swe[o*4]*at0 + swe[o*4+1]*at1 + swe[o*4+2]*at2 + swe[o*4+3]*at3;
        const float4* w4 = reinterpret_cast<const float4*>(&swf1t[o*16]);
        float4 wa = w4[0], wb = w4[1], wc4 = w4[2], wd = w4[3];
        acc[0]  += wa.x*yv;  acc[1]  += wa.y*yv;  acc[2]  += wa.z*yv;  acc[3]  += wa.w*yv;
        acc[4]  += wb.x*yv;  acc[5]  += wb.y*yv;  acc[6]  += wb.z*yv;  acc[7]  += wb.w*yv;
        acc[8]  += wc4.x*yv; acc[9]  += wc4.y*yv; acc[10] += wc4.z*yv; acc[11] += wc4.w*yv;
        acc[12] += wd.x*yv;  acc[13] += wd.y*yv;  acc[14] += wd.z*yv;  acc[15] += wd.w*yv;
    }
    float* sp = &sred[(g*64 + pixl)*17];
    #pragma unroll
    for (int m = 0; m < 16; m++) sp[m] = acc[m];
    __syncthreads();

    // thread (g,pixl) finalizes h1 channels m = g*4 .. g*4+3, writes PADDED h1
    int col = wbase + pixl;
    #pragma unroll
    for (int i = 0; i < 4; i++) {
        int m = g*4 + i;
        float h = sbf1[m];
        #pragma unroll
        for (int gg = 0; gg < 4; gg++) h += sred[(gg*64 + pixl)*17 + m];
        g_h1p[(b*16 + m)*PH1 + (row + 5)*PCOLS + (col + 2)] = fmaxf(h, 0.f);
    }
}

// ---------------- fused: dilated 3x3 conv + relu + final 1x1 + residual ----------------
// grid 512, block 256 = 4 groups x 64 pixels; branchless conv via padded h1.
// Epilogue reconstructs y = x + weff2@att + beff2 inline (y buffer eliminated).
__global__ void __launch_bounds__(256, 4)
h2out_kernel(const float* __restrict__ x,
             const float* __restrict__ wf2, const float* __restrict__ bf2,
             const float* __restrict__ wf3, const float* __restrict__ bf3,
             float* __restrict__ out) {
    __shared__ __align__(16) float sw2t[2304];  // [ci][tap][m]
    __shared__ float sb[16];
    __shared__ __align__(16) float sw3[1024];   // [o][m]
    __shared__ float sb3[64];
    __shared__ float swe2[256], sbe2[64];
    __shared__ float satt4[256];
    __shared__ float sred[4*64*17];
    __shared__ float sfin[64*17];
    int t = threadIdx.x;
    for (int i = t; i < 2304; i += 256) {
        int ci = i / 144, rem = i - ci*144;
        int tap = rem >> 4, m = rem & 15;
        sw2t[i] = wf2[(m*16 + ci)*9 + tap];
    }
    for (int i = t; i < 1024; i += 256) sw3[i] = wf3[i];
    if (t < 16) sb[t] = bf2[t];
    if (t < 64) sb3[t] = bf3[t];

    cudaGridDependencySynchronize();     // h1_kernel complete beyond this point

    int pbase = blockIdx.x * 64;
    int b = pbase >> 14;
    int pixbase = pbase & 16383;
    swe2[t] = g_weff2[t];
    if (t < 64) sbe2[t] = g_beff2[t];
    satt4[t] = g_att[(b*4 + (t >> 6))*HW + pixbase + (t & 63)];
    __syncthreads();

    int g = t >> 6, pixl = t & 63;
    int pix = pixbase + pixl;
    int h = pix >> 7, w = pix & 127;

    float vload[4][9];
    #pragma unroll
    for (int i = 0; i < 4; i++) {
        int ci = g*4 + i;
        const float* tb = &g_h1p[(b*16 + ci)*PH1];
        #pragma unroll
        for (int kh = 0; kh < 3; kh++)
            #pragma unroll
            for (int kw = 0; kw < 3; kw++)
                vload[i][kh*3+kw] = tb[(h + 2*kh)*PCOLS + (w + 2*kw)];
    }

    float acc[16];
    #pragma unroll
    for (int m = 0; m < 16; m++) acc[m] = 0.f;
    #pragma unroll
    for (int i = 0; i < 4; i++) {
        int ci = g*4 + i;
        const float* wb = &sw2t[ci*144];
        #pragma unroll
        for (int tap = 0; tap < 9; tap++) {
            float v = vload[i][tap];
            const float4* w4 = reinterpret_cast<const float4*>(&wb[tap*16]);
            float4 wa = w4[0], wbv = w4[1], wcv = w4[2], wd = w4[3];
            acc[0]  += wa.x*v;  acc[1]  += wa.y*v;  acc[2]  += wa.z*v;  acc[3]  += wa.w*v;
            acc[4]  += wbv.x*v; acc[5]  += wbv.y*v; acc[6]  += wbv.z*v; acc[7]  += wbv.w*v;
            acc[8]  += wcv.x*v; acc[9]  += wcv.y*v; acc[10] += wcv.z*v; acc[11] += wcv.w*v;
            acc[12] += wd.x*v;  acc[13] += wd.y*v;  acc[14] += wd.z*v;  acc[15] += wd.w*v;
        }
    }
    float* sp = &sred[(g*64 + pixl)*17];
    #pragma unroll
    for (int m = 0; m < 16; m++) sp[m] = acc[m];
    __syncthreads();

    #pragma unroll
    for (int i = 0; i < 4; i++) {
        int m = g*4 + i;
        float v = sb[m];
        #pragma unroll
        for (int gg = 0; gg < 4; gg++) v += sred[(gg*64 + pixl)*17 + m];
        sfin[pixl*17 + m] = fmaxf(v, 0.f);
    }
    __syncthreads();

    float h2v[16];
    #pragma unroll
    for (int m = 0; m < 16; m++) h2v[m] = sfin[pixl*17 + m];
    float at0 = satt4[pixl], at1 = satt4[64+pixl], at2 = satt4[128+pixl], at3 = satt4[192+pixl];
    const float* xp = x + b*64*HW + pix;
    float*       op = out + b*64*HW + pix;
    #pragma unroll
    for (int i = 0; i < 16; i++) {
        int o = g*16 + i;
        const float4* w4 = reinterpret_cast<const float4*>(&sw3[o*16]);
        float4 wa = w4[0], wbv = w4[1], wcv = w4[2], wd = w4[3];
        float s = xp[o*HW] + sbe2[o] + sb3[o]
                + swe2[o*4]*at0 + swe2[o*4+1]*at1 + swe2[o*4+2]*at2 + swe2[o*4+3]*at3;
        s += wa.x*h2v[0]   + wa.y*h2v[1]   + wa.z*h2v[2]   + wa.w*h2v[3];
        s += wbv.x*h2v[4]  + wbv.y*h2v[5]  + wbv.z*h2v[6]  + wbv.w*h2v[7];
        s += wcv.x*h2v[8]  + wcv.y*h2v[9]  + wcv.z*h2v[10] + wcv.w*h2v[11];
        s += wd.x*h2v[12]  + wd.y*h2v[13]  + wd.z*h2v[14]  + wd.w*h2v[15];
        op[o*HW] = s;
    }
}

extern "C" void kernel_launch(void* const* d_in, const int* in_sizes, int n_in,
                              void* d_out, int out_size) {
    const float* x   = (const float*)d_in[0];
    const float* w1a = (const float*)d_in[1];
    const float* b1a = (const float*)d_in[2];
    const float* w1b = (const float*)d_in[3];
    const float* b1b = (const float*)d_in[4];
    const float* wqk = (const float*)d_in[5];
    const float* w2  = (const float*)d_in[6];
    const float* b2  = (const float*)d_in[7];
    const float* wc  = (const float*)d_in[8];
    const float* bc  = (const float*)d_in[9];
    const float* wf1 = (const float*)d_in[10];
    const float* bf1 = (const float*)d_in[11];
    const float* wf2 = (const float*)d_in[12];
    const float* bf2 = (const float*)d_in[13];
    const float* wf3 = (const float*)d_in[14];
    const float* bf3 = (const float*)d_in[15];
    float* out = (float*)d_out;

    a_kernel<<<513, 256>>>(x, w1a, b1a, w1b, b1b, w2, b2, wc, bc);

    cudaLaunchAttribute attr[1];
    attr[0].id = cudaLaunchAttributeProgrammaticStreamSerialization;
    attr[0].val.programmaticStreamSerializationAllowed = 1;

    {
        cudaLaunchConfig_t cfg = {};
        cfg.gridDim = dim3(4, 32); cfg.blockDim = dim3(384);
        cfg.stream = 0; cfg.attrs = attr; cfg.numAttrs = 1;
        cudaLaunchKernelEx(&cfg, attn1_kernel, wqk);
    }
    {
        cudaLaunchConfig_t cfg = {};
        cfg.gridDim = dim3(512); cfg.blockDim = dim3(256);
        cfg.stream = 0; cfg.attrs = attr; cfg.numAttrs = 1;
        cudaLaunchKernelEx(&cfg, h1_kernel, x, wf1, bf1);
    }
    {
        cudaLaunchConfig_t cfg = {};
        cfg.gridDim = dim3(512); cfg.blockDim = dim3(256);
        cfg.stream = 0; cfg.attrs = attr; cfg.numAttrs = 1;
        cudaLaunchKernelEx(&cfg, h2out_kernel, x, wf2, bf2, wf3, bf3, out);
    }
}